// round 9
// baseline (speedup 1.0000x reference)
#include <cuda_runtime.h>
#include <cuda_bf16.h>
#include <cstdint>

// Problem constants (HungarianMatcher_8650064134686)
#define BS   64
#define NQ   300
#define TT   1280                     // total targets
#define ROWS (BS * NQ)                // 19200
#define ROWS_PER_BLOCK 16
#define THREADS 320                   // TT / 4 targets per thread
#define GRID (ROWS / ROWS_PER_BLOCK)  // 1200

#define RCPA(out, in) \
    asm("rcp.approx.f32 %0, %1;" : "=f"(out) : "f"(in))

// Closed-form 1-D GIoU (verified in both overlap and disjoint regimes):
//   giou = (min(x2,tx2) - max(x1,tx1)) / (max(x2,tx2) - min(x1,tx1))
// cost = |cx-tcx| + |w-tw| + (refdist - prob_fg) - giou
// Scalar throughout: 7 FMA-pipe + 4 FMNMX(alu) + 1 MUFU per element, zero MOVs.

__global__ __launch_bounds__(THREADS)
void matcher_cost_kernel(const float* __restrict__ logits,   // [ROWS, 2]
                         const float* __restrict__ spans,    // [ROWS, 2]
                         const float* __restrict__ tgt,      // [TT, 2]
                         const float* __restrict__ refp,     // [ROWS, 2]
                         float* __restrict__ out)            // [ROWS, TT]
{
    __shared__ float4 s_cwxx[ROWS_PER_BLOCK];  // (cx, w, x1, x2)
    __shared__ float  s_rc  [ROWS_PER_BLOCK];  // rd - prob

    const int t    = threadIdx.x;
    const int row0 = blockIdx.x * ROWS_PER_BLOCK;

    if (t < ROWS_PER_BLOCK) {
        const int r = row0 + t;
        const float cx = spans[2 * r + 0];
        const float w  = spans[2 * r + 1];
        const float x1 = cx - 0.5f * w;
        const float x2 = cx + 0.5f * w;
        const float l0 = logits[2 * r + 0];
        const float l1 = logits[2 * r + 1];
        const float prob = 1.0f / (1.0f + __expf(l1 - l0));  // softmax fg (NC=2)
        const float dx = x1 - refp[2 * r + 0];
        const float dy = x2 - refp[2 * r + 1];
        const float rd = sqrtf(fmaf(dx, dx, dy * dy));
        float4 cw; cw.x = cx; cw.y = w; cw.z = x1; cw.w = x2;
        s_cwxx[t] = cw;
        s_rc  [t] = rd - prob;
    }

    // Per-thread targets: 4 consecutive, fully register-resident.
    const float4* tg4 = reinterpret_cast<const float4*>(tgt);
    const float4 ta = tg4[2 * t + 0];   // (cx0, w0, cx1, w1)
    const float4 tb = tg4[2 * t + 1];   // (cx2, w2, cx3, w3)

    float tcx[4] = {ta.x, ta.z, tb.x, tb.z};
    float tw [4] = {ta.y, ta.w, tb.y, tb.w};
    float tx1[4], tx2[4];
#pragma unroll
    for (int j = 0; j < 4; ++j) {
        tx1[j] = tcx[j] - 0.5f * tw[j];
        tx2[j] = tcx[j] + 0.5f * tw[j];
    }

    __syncthreads();

    float4* orow = reinterpret_cast<float4*>(out) + (size_t)row0 * (TT / 4) + t;

#pragma unroll
    for (int rr = 0; rr < ROWS_PER_BLOCK; ++rr) {
        const float4 cw = s_cwxx[rr];   // LDS.128
        const float  rc = s_rc  [rr];   // LDS.32

        float res[4];
#pragma unroll
        for (int j = 0; j < 4; ++j) {
            const float d    = cw.x - tcx[j];              // FADD
            const float wd   = cw.y - tw[j];               // FADD
            const float l1c  = fabsf(d) + fabsf(wd);       // FADD |a|,|b|
            const float base = l1c + rc;                   // FADD
            const float lt = fmaxf(cw.z, tx1[j]);          // FMNMX (alu)
            const float rb = fminf(cw.w, tx2[j]);          // FMNMX (alu)
            const float le = fminf(cw.z, tx1[j]);          // FMNMX (alu)
            const float ri = fmaxf(cw.w, tx2[j]);          // FMNMX (alu)
            const float nn = lt - rb;                      // FADD  (= -num)
            const float de = ri - le;                      // FADD
            float r; RCPA(r, de);                          // MUFU.RCP
            res[j] = fmaf(nn, r, base);                    // FFMA: base - num/den
        }

        float4 o;
        o.x = res[0]; o.y = res[1]; o.z = res[2]; o.w = res[3];
        *orow = o;
        orow += TT / 4;
    }
}

extern "C" void kernel_launch(void* const* d_in, const int* in_sizes, int n_in,
                              void* d_out, int out_size)
{
    const float* pred_logits = (const float*)d_in[0];  // [BS, NQ, 2]
    const float* pred_spans  = (const float*)d_in[1];  // [BS, NQ, 2]
    const float* tgt_spans   = (const float*)d_in[2];  // [TT, 2]
    const float* ref_points  = (const float*)d_in[3];  // [BS, NQ, 2]
    float*       out         = (float*)d_out;          // [BS, NQ, TT]

    matcher_cost_kernel<<<GRID, THREADS>>>(pred_logits, pred_spans,
                                           tgt_spans, ref_points, out);
}